// round 6
// baseline (speedup 1.0000x reference)
#include <cuda_runtime.h>
#include <cstdint>

#define N_NODES 100000
#define N_EDGES 1600000
#define N_PRED  500000
#define D       64
#define NB_SCAN 391   // ceil(N_NODES/256)

// ---------------- device scratch (alloc-free rule: static globals) ----------
__device__ int   g_deg_out[N_NODES];
__device__ int   g_deg_in [N_NODES];
__device__ float g_norm_out[N_NODES];
__device__ float g_norm_in [N_NODES];
__device__ int2  g_rowdeg  [N_NODES];   // (rowstart, deg_in) packed
__device__ int   g_rowstart[N_NODES];   // scan intermediate
__device__ int   g_cursor  [N_NODES];
__device__ int   g_blocksum[NB_SCAN];
__device__ int   g_blockoff[NB_SCAN];
__device__ int   g_csr_src [N_EDGES];
__device__ __align__(16) float g_xn [(size_t)N_NODES * D]; // layer-2 input (pre-scaled)
__device__ __align__(16) float g_agg[(size_t)N_NODES * D]; // aggregated (incl. norm_in)
__device__ __align__(16) float g_p  [(size_t)N_NODES * 16];// [pA | pB] per node

// ---------------- degree --------------------------------------------------

__global__ void k_zero_deg() {
    int i = blockIdx.x * blockDim.x + threadIdx.x;
    if (i < N_NODES) { g_deg_out[i] = 0; g_deg_in[i] = 0; }
}

__global__ void k_degree(const int* __restrict__ src, const int* __restrict__ dst) {
    int e = blockIdx.x * blockDim.x + threadIdx.x;
    if (e < N_EDGES) {
        atomicAdd(&g_deg_out[__ldg(&src[e])], 1);
        atomicAdd(&g_deg_in [__ldg(&dst[e])], 1);
    }
}

// ---------------- exclusive scan of deg_in -> rowstart ----------------------

__global__ void k_scan1() {
    __shared__ int sh[256];
    int i = blockIdx.x * 256 + threadIdx.x;
    int v = (i < N_NODES) ? g_deg_in[i] : 0;
    sh[threadIdx.x] = v;
    __syncthreads();
#pragma unroll
    for (int off = 1; off < 256; off <<= 1) {
        int t = (threadIdx.x >= off) ? sh[threadIdx.x - off] : 0;
        __syncthreads();
        sh[threadIdx.x] += t;
        __syncthreads();
    }
    if (i < N_NODES) g_rowstart[i] = sh[threadIdx.x] - v;   // exclusive
    if (threadIdx.x == 255) g_blocksum[blockIdx.x] = sh[255];
}

__global__ void k_scan2() {   // single block of 512, scans NB_SCAN block sums
    __shared__ int sh[512];
    int v = (threadIdx.x < NB_SCAN) ? g_blocksum[threadIdx.x] : 0;
    sh[threadIdx.x] = v;
    __syncthreads();
#pragma unroll
    for (int off = 1; off < 512; off <<= 1) {
        int t = (threadIdx.x >= off) ? sh[threadIdx.x - off] : 0;
        __syncthreads();
        sh[threadIdx.x] += t;
        __syncthreads();
    }
    if (threadIdx.x < NB_SCAN) g_blockoff[threadIdx.x] = sh[threadIdx.x] - v;  // exclusive
}

// finalize rowstart/cursor (packed) AND compute norms (fused)
__global__ void k_scan3_norms() {
    int i = blockIdx.x * blockDim.x + threadIdx.x;
    if (i < N_NODES) {
        int din = g_deg_in[i];
        int rs = g_rowstart[i] + g_blockoff[i >> 8];
        g_rowdeg[i] = make_int2(rs, din);
        g_cursor[i] = rs;
        int dou = g_deg_out[i];
        g_norm_out[i] = dou > 0 ? rsqrtf((float)dou) : 0.f;
        g_norm_in [i] = din > 0 ? rsqrtf((float)din) : 0.f;
    }
}

// ---------------- CSR bucket fill -------------------------------------------

__global__ void k_bucket(const int* __restrict__ src, const int* __restrict__ dst) {
    int e = blockIdx.x * blockDim.x + threadIdx.x;
    if (e < N_EDGES) {
        int d = __ldg(&dst[e]);
        int pos = atomicAdd(&g_cursor[d], 1);
        g_csr_src[pos] = __ldg(&src[e]);
    }
}

// ---------------- pull-mode aggregation -------------------------------------
// One warp per dst node; the two half-warps process neighbors k and k+1
// concurrently, each lane loading a float4 (16 lanes x 16B = 256B row).
// unroll 8 => up to 8 independent LDG.128 per lane in flight.
template <int SRC_X>
__global__ void __launch_bounds__(256)
k_aggregate(const float* __restrict__ xin) {
    int warp = (blockIdx.x * blockDim.x + threadIdx.x) >> 5;
    int lane = threadIdx.x & 31;
    if (warp >= N_NODES) return;

    const float* in = SRC_X ? xin : (const float*)g_xn;
    const int half = lane >> 4;   // which neighbor of the pair
    const int col  = lane & 15;   // float4 column within the row

    int2 rd = __ldg(&g_rowdeg[warp]);
    int start = rd.x;
    int deg   = rd.y;
    float4 acc = make_float4(0.f, 0.f, 0.f, 0.f);

    for (int base = 0; base < deg; base += 32) {
        int my = base + lane;
        int s_my = (my < deg) ? __ldg(&g_csr_src[start + my]) : 0;
        int cnt = min(32, deg - base);
#pragma unroll 8
        for (int k2 = 0; k2 < cnt; k2 += 2) {
            int idx = k2 + half;
            int s = __shfl_sync(0xffffffffu, s_my, idx & 31);
            if (idx < cnt) {
                float4 v = ((const float4*)(in + (size_t)s * D))[col];
                if (SRC_X) {
                    float no = __ldg(&g_norm_out[s]);
                    v.x *= no; v.y *= no; v.z *= no; v.w *= no;
                }
                acc.x += v.x; acc.y += v.y; acc.z += v.z; acc.w += v.w;
            }
        }
    }
    acc.x += __shfl_xor_sync(0xffffffffu, acc.x, 16);
    acc.y += __shfl_xor_sync(0xffffffffu, acc.y, 16);
    acc.z += __shfl_xor_sync(0xffffffffu, acc.z, 16);
    acc.w += __shfl_xor_sync(0xffffffffu, acc.w, 16);

    if (half == 0) {
        float ni = g_norm_in[warp];
        acc.x *= ni; acc.y *= ni; acc.z *= ni; acc.w *= ni;
        ((float4*)(g_agg + (size_t)warp * D))[col] = acc;
    }
}

// ---------------- layer-1 node GEMM update ----------------------------------
// g_xn = relu(g_agg @ W1 + b1) * norm_out
__global__ void __launch_bounds__(256, 2)
k_node_update1(const float* __restrict__ W, const float* __restrict__ b) {
    const int t = threadIdx.x;
    const int c = t & 63;
    const int r = t >> 6;

    float w[D];
#pragma unroll
    for (int kk = 0; kk < D; kk++) w[kk] = __ldg(&W[kk * D + c]);
    const float bc = __ldg(&b[c]);

    __shared__ __align__(16) float vs[4][D];

    for (int base = blockIdx.x * 4; base < N_NODES; base += gridDim.x * 4) {
        int node = base + r;
        bool ok = (node < N_NODES);
        size_t off = (size_t)(ok ? node : 0) * D + c;
        if (ok) vs[r][c] = g_agg[off];
        __syncthreads();

        float acc = bc;
        const float4* vrow = (const float4*)vs[r];
#pragma unroll
        for (int q = 0; q < D / 4; q++) {
            float4 vv = vrow[q];
            acc = fmaf(vv.x, w[4 * q + 0], acc);
            acc = fmaf(vv.y, w[4 * q + 1], acc);
            acc = fmaf(vv.z, w[4 * q + 2], acc);
            acc = fmaf(vv.w, w[4 * q + 3], acc);
        }
        if (ok) {
            acc = fmaxf(acc, 0.f) * g_norm_out[node];
            g_xn[off] = acc;
        }
        __syncthreads();
    }
}

// ---------------- fused layer-2 GEMM + predictor projection -----------------
// h = g_agg @ W2 + b2 (never written to gmem);
// g_p[n][c] = sum_k h[n][k] * Wp[(rowoff(c)+k)*8 + (c&7)], rowoff = c<8?0:64.
__global__ void __launch_bounds__(256, 2)
k_update2_project(const float* __restrict__ W, const float* __restrict__ b,
                  const float* __restrict__ Wp) {
    const int t = threadIdx.x;
    const int c = t & 63;
    const int r = t >> 6;

    float w[D];
#pragma unroll
    for (int kk = 0; kk < D; kk++) w[kk] = __ldg(&W[kk * D + c]);
    const float bc = __ldg(&b[c]);

    __shared__ __align__(16) float vs[4][D];   // staged agg rows
    __shared__ __align__(16) float hs[4][D];   // computed h rows
    __shared__ float wps[D][16];               // permuted Wp: wps[k][c2]

    // stage Wp once: 1024 entries / 256 threads = 4 each
#pragma unroll
    for (int q = 0; q < 4; q++) {
        int idx = t + q * 256;        // idx = k*16 + c2
        int k  = idx >> 4;
        int c2 = idx & 15;
        int rowoff = (c2 < 8) ? 0 : 64;
        wps[k][c2] = __ldg(&Wp[(rowoff + k) * 8 + (c2 & 7)]);
    }
    __syncthreads();

    // projection thread mapping: 4 lanes per output
    const int out_idx = t >> 2;          // 0..63: node slot (out_idx>>4), col (out_idx&15)
    const int part    = t & 3;           // k-range [part*16, part*16+16)
    const int pr      = out_idx >> 4;    // node slot 0..3
    const int pc      = out_idx & 15;    // output col 0..15

    for (int base = blockIdx.x * 4; base < N_NODES; base += gridDim.x * 4) {
        int node = base + r;
        bool ok = (node < N_NODES);
        size_t off = (size_t)(ok ? node : 0) * D + c;
        if (ok) vs[r][c] = g_agg[off];
        __syncthreads();

        float acc = bc;
        const float4* vrow = (const float4*)vs[r];
#pragma unroll
        for (int q = 0; q < D / 4; q++) {
            float4 vv = vrow[q];
            acc = fmaf(vv.x, w[4 * q + 0], acc);
            acc = fmaf(vv.y, w[4 * q + 1], acc);
            acc = fmaf(vv.z, w[4 * q + 2], acc);
            acc = fmaf(vv.w, w[4 * q + 3], acc);
        }
        hs[r][c] = acc;                  // ok-ness handled at projection store
        __syncthreads();

        // projection: p = h @ wps, 4-way split over k then shfl-combine
        float ps = 0.f;
#pragma unroll
        for (int i = 0; i < 16; i++) {
            int k = part * 16 + i;
            ps = fmaf(hs[pr][k], wps[k][pc], ps);
        }
        ps += __shfl_xor_sync(0xffffffffu, ps, 1);
        ps += __shfl_xor_sync(0xffffffffu, ps, 2);
        int pnode = base + pr;
        if (part == 0 && pnode < N_NODES)
            g_p[(size_t)pnode * 16 + pc] = ps;
        __syncthreads();
    }
}

// ---------------- final edge scores -----------------------------------------

__global__ void k_edge_pred(const int* __restrict__ psrc, const int* __restrict__ pdst,
                            const float* __restrict__ bp, float* __restrict__ out) {
    int e = blockIdx.x * blockDim.x + threadIdx.x;
    if (e >= N_PRED) return;
    int u = __ldg(&psrc[e]);
    int v = __ldg(&pdst[e]);
    const float4* pa = (const float4*)(g_p + (size_t)u * 16);
    const float4* pb = (const float4*)(g_p + (size_t)v * 16 + 8);
    float4 a0 = pa[0], a1 = pa[1];
    float4 c0 = pb[0], c1 = pb[1];
    float4 bp0 = ((const float4*)bp)[0];
    float4 bp1 = ((const float4*)bp)[1];
    float4 o0 = make_float4(a0.x + c0.x + bp0.x, a0.y + c0.y + bp0.y,
                            a0.z + c0.z + bp0.z, a0.w + c0.w + bp0.w);
    float4 o1 = make_float4(a1.x + c1.x + bp1.x, a1.y + c1.y + bp1.y,
                            a1.z + c1.z + bp1.z, a1.w + c1.w + bp1.w);
    ((float4*)out)[(size_t)e * 2 + 0] = o0;
    ((float4*)out)[(size_t)e * 2 + 1] = o1;
}

// ---------------- launch ----------------------------------------------------

extern "C" void kernel_launch(void* const* d_in, const int* in_sizes, int n_in,
                              void* d_out, int out_size) {
    const float* x    = (const float*)d_in[0];
    const int*   src  = (const int*)  d_in[1];
    const int*   dst  = (const int*)  d_in[2];
    const int*   psrc = (const int*)  d_in[3];
    const int*   pdst = (const int*)  d_in[4];
    const float* W1   = (const float*)d_in[5];
    const float* b1   = (const float*)d_in[6];
    const float* W2   = (const float*)d_in[7];
    const float* b2   = (const float*)d_in[8];
    const float* Wp   = (const float*)d_in[9];
    const float* bp   = (const float*)d_in[10];
    float* out = (float*)d_out;

    const int TB = 256;
    // degrees
    k_zero_deg<<<(N_NODES + TB - 1) / TB, TB>>>();
    k_degree  <<<(N_EDGES + TB - 1) / TB, TB>>>(src, dst);

    // CSR build (by dst) + norms
    k_scan1<<<NB_SCAN, 256>>>();
    k_scan2<<<1, 512>>>();
    k_scan3_norms<<<(N_NODES + TB - 1) / TB, TB>>>();
    k_bucket<<<(N_EDGES + TB - 1) / TB, TB>>>(src, dst);

    const int AGG_BLOCKS = N_NODES * 32 / TB;  // one warp per node, exact

    // layer 1
    k_aggregate<1><<<AGG_BLOCKS, TB>>>(x);
    k_node_update1<<<1024, TB>>>(W1, b1);            // -> g_xn (relu * norm_out)

    // layer 2 (GEMM fused with predictor projection; g_h never materialized)
    k_aggregate<0><<<AGG_BLOCKS, TB>>>(nullptr);
    k_update2_project<<<1024, TB>>>(W2, b2, Wp);     // -> g_p

    // predictor
    k_edge_pred<<<(N_PRED + TB - 1) / TB, TB>>>(psrc, pdst, bp, out);
}